// round 15
// baseline (speedup 1.0000x reference)
#include <cuda_runtime.h>
#include <cuda_fp16.h>
#include <cstdint>

typedef uint32_t u32;

#define Bb 8
#define Mm 2048
#define NNs 2048
#define Dd 128
#define BM 128
#define BN 64
#define TPB 512
#define NCT 512
#define NT 32

#define C2 0.7213475204444817f   /* 0.5 * log2(e) */
#define INV_KEEP 1.25f

// pre-split fp16 copies of x1/x2 (hi/lo), packed u32 pairs, linear layout
__device__ u32 gQH[Bb*Mm*Dd/2], gQL[Bb*Mm*Dd/2];
__device__ u32 gKH[Bb*NNs*Dd/2], gKL[Bb*NNs*Dd/2];
// keep-bit words: index = (b*2048+row)*64 + col_word; bit j = col col_word*32+j
__device__ u32 gMK[Bb*Mm*NNs/32];

// ---- smem byte offsets (attention kernel) ----
#define OF_QH   0        /* 128x128 fp16 = 32KB */
#define OF_QL   32768
#define OF_K0   65536    /* 3 x (KH 16KB + KL 16KB) ring */
#define OF_P0   163840   /* 2 x PH(fp16) 16KB ring */
#define OF_RED  196608   /* 128 rows x 2 floats */
#define OF_BAR  197632   /* mbarriers: KF0-2, KE0-2 (6 x 8B) */
#define SMEM_TOTAL 197760

#define BKF(i) (smb + OF_BAR + (u32)(i)*8u)
#define BKE(i) (smb + OF_BAR + 24u + (u32)(i)*8u)

__device__ __forceinline__ void mwait(u32 addr, u32 ph){
    u32 done;
    asm volatile("{\n\t.reg .pred p;\n\t"
        "mbarrier.try_wait.parity.acquire.cta.shared::cta.b64 p, [%1], %2;\n\t"
        "selp.b32 %0, 1, 0, p;\n\t}"
        : "=r"(done) : "r"(addr), "r"(ph) : "memory");
    if (!done){
        asm volatile("{\n\t.reg .pred P1;\n\t"
            "WL_%=:\n\t"
            "mbarrier.try_wait.parity.acquire.cta.shared::cta.b64 P1, [%0], %1, 0x989680;\n\t"
            "@P1 bra.uni WD_%=;\n\t"
            "bra.uni WL_%=;\n\t"
            "WD_%=:\n\t}"
            :: "r"(addr), "r"(ph) : "memory");
    }
}
__device__ __forceinline__ void marr(u32 addr){
    asm volatile("mbarrier.arrive.shared.b64 _, [%0];" :: "r"(addr) : "memory");
}
__device__ __forceinline__ void mcparr(u32 addr){
    asm volatile("cp.async.mbarrier.arrive.noinc.shared::cta.b64 [%0];" :: "r"(addr) : "memory");
}
__device__ __forceinline__ void bar_pair(int id){
    asm volatile("bar.sync %0, 64;" :: "r"(id) : "memory");
}

__device__ __forceinline__ u32 swa(u32 base, int row, int colb){
    return base + (u32)(row * 256) + (u32)((((colb >> 4) ^ (row & 7)) << 4) + (colb & 15));
}
__device__ __forceinline__ u32 swp(u32 base, int row, int colb){
    return base + (u32)(row * 128) + (u32)(((((colb >> 4) ^ (row & 7)) & 7) << 4) + (colb & 15));
}
__device__ __forceinline__ void ldsm4(u32* r, u32 a){
    asm volatile("ldmatrix.sync.aligned.m8n8.x4.shared.b16 {%0,%1,%2,%3},[%4];"
        : "=r"(r[0]),"=r"(r[1]),"=r"(r[2]),"=r"(r[3]) : "r"(a));
}
__device__ __forceinline__ void ldsm4t(u32* r, u32 a){
    asm volatile("ldmatrix.sync.aligned.m8n8.x4.trans.shared.b16 {%0,%1,%2,%3},[%4];"
        : "=r"(r[0]),"=r"(r[1]),"=r"(r[2]),"=r"(r[3]) : "r"(a));
}
__device__ __forceinline__ void mmaf16(float* c, const u32* a, u32 b0, u32 b1){
    asm volatile("mma.sync.aligned.m16n8k16.row.col.f32.f16.f16.f32 "
        "{%0,%1,%2,%3},{%4,%5,%6,%7},{%8,%9},{%0,%1,%2,%3};"
        : "+f"(c[0]),"+f"(c[1]),"+f"(c[2]),"+f"(c[3])
        : "r"(a[0]),"r"(a[1]),"r"(a[2]),"r"(a[3]),"r"(b0),"r"(b1));
}
__device__ __forceinline__ void split16(float p0, float p1, u32& h2, u32& l2){
    __half2 h = __floats2half2_rn(p0, p1);
    h2 = *(u32*)&h;
    float r0 = p0 - __low2float(h);
    float r1 = p1 - __high2float(h);
    __half2 l = __floats2half2_rn(r0, r1);
    l2 = *(u32*)&l;
}
__device__ __forceinline__ u32 packh(float a, float b){
    __half2 h = __floats2half2_rn(a, b);
    return *(u32*)&h;
}
__device__ __forceinline__ float ex2f(float x){
    float r; asm("ex2.approx.f32 %0, %1;" : "=f"(r) : "f"(x)); return r;
}

// JAX threefry2x32 partitionable, bit-exact (frozen; validated in R14).
// c = ctr + 42; round 1 simplified since x0 starts at 0.
__device__ __forceinline__ u32 tf_keep_c(u32 c)
{
    const u32 K1 = 42u;
    const u32 K2 = 0x1BD11BDAu ^ 42u;
    u32 x0 = c;
    u32 x1 = __funnelshift_l(c, c, 13) ^ c;
#define TF_RND(r) { x0 += x1; x1 = __funnelshift_l(x1, x1, (r)); x1 ^= x0; }
    TF_RND(15) TF_RND(26) TF_RND(6)
    x0 += K1; x1 += K2 + 1u;
    TF_RND(17) TF_RND(29) TF_RND(16) TF_RND(24)
    x0 += K2; x1 += 0u + 2u;
    TF_RND(13) TF_RND(15) TF_RND(26) TF_RND(6)
    x0 += 0u; x1 += K1 + 3u;
    TF_RND(17) TF_RND(29) TF_RND(16) TF_RND(24)
    x0 += K1; x1 += K2 + 4u;
    TF_RND(13) TF_RND(15) TF_RND(26) TF_RND(6)
    x0 += K2; x1 += 0u + 5u;
#undef TF_RND
    return (((x0 ^ x1) >> 9) <= 6710886u) ? 1u : 0u;
}

// ---------------------------------------------------------------------------
// Kernel A: split x1/x2 -> fp16 hi/lo  AND  generate all keep-bit words.
// Thread i: float4 #i of (x1|x2)  +  mask word #i.  1M threads.
// ---------------------------------------------------------------------------
__global__ void __launch_bounds__(256)
split_mask(const float* __restrict__ x1, const float* __restrict__ x2)
{
    int i = blockIdx.x * 256 + threadIdx.x;

    // ---- split part (memory-bound) ----
    {
        int half = i >> 19;
        int j = i & 0x7FFFF;
        const float4* src = (const float4*)(half ? x2 : x1);
        float4 v = src[j];
        u32 h0,l0,h1,l1;
        split16(v.x, v.y, h0, l0);
        split16(v.z, v.w, h1, l1);
        uint2* dh = (uint2*)(half ? gKH : gQH);
        uint2* dl = (uint2*)(half ? gKL : gQL);
        dh[j] = make_uint2(h0, h1);
        dl[j] = make_uint2(l0, l1);
    }

    // ---- mask part (alu-bound): word i = 32 keep bits ----
    {
        u32 rowg = (u32)i >> 6;          // global row 0..16383
        u32 colw = (u32)i & 63u;
        u32 cbase = rowg * 2048u + colw * 32u + 42u;
        u32 m = 0;
        #pragma unroll 8
        for (int j = 0; j < 32; j++)
            m |= tf_keep_c(cbase + (u32)j) << j;
        gMK[i] = m;
    }
}

// cp.async one 64-row fp16 K tile pair (hi+lo); 512 threads, 4 chunks each
__device__ __forceinline__ void cp_k(u32 bufbase, int b, int n0, int tid){
    #pragma unroll
    for (int k = 0; k < 4; k++){
        int idx  = tid + k * NCT;
        int half = idx >> 10;
        int ci   = idx & 1023;
        int row  = ci >> 4;
        int c    = ci & 15;
        u32 da = bufbase + (u32)(half * 16384) + (u32)(row * 256) + (u32)((c ^ (row & 7)) << 4);
        const char* s = (const char*)(half ? gKL : gKH)
                      + ((size_t)(b * NNs + n0 + row) * 256 + c * 16);
        asm volatile("cp.async.cg.shared.global [%0], [%1], 16;" :: "r"(da), "l"(s));
    }
}

// PV step (single pass fp16): O += P16 * V16  (V16 = fp16 K-hi tile, trans)
__device__ __forceinline__ void pv_step(float o[8][4], u32 PHb, u32 KHb,
                                        int g, int s, int rA, int cA){
    #pragma unroll
    for (int kk = 0; kk < 4; kk++){
        u32 pA[4];
        ldsm4(pA, swp(PHb, 16 * g + rA, 32 * kk + cA));
        #pragma unroll
        for (int dgp = 0; dgp < 4; dgp++){
            int colb = 128 * s + 32 * dgp + cA;
            u32 bh[4];
            ldsm4t(bh, swa(KHb, 16 * kk + rA, colb));
            mmaf16(o[2*dgp],   pA, bh[0], bh[1]);
            mmaf16(o[2*dgp+1], pA, bh[2], bh[3]);
        }
    }
}

// ---------------------------------------------------------------------------
// Kernel B: attention. 512 threads = 16 compute warps. Masks via __ldg.
// ---------------------------------------------------------------------------
__global__ void __launch_bounds__(TPB, 1)
attn_hmma(const float* __restrict__ x1, const float* __restrict__ x2, float* __restrict__ out)
{
    extern __shared__ char sm[];
    const u32 smb = (u32)__cvta_generic_to_shared(sm);
    const int tid  = threadIdx.x;
    const int w    = tid >> 5;
    const int lane = tid & 31;
    const int gID  = lane >> 2;
    const int tig  = lane & 3;
    const int b    = blockIdx.y;
    const int mrow0 = blockIdx.x * BM;

    if (tid == 0){
        #pragma unroll
        for (int i = 0; i < 3; i++){
            asm volatile("mbarrier.init.shared.b64 [%0], %1;" :: "r"(BKF(i)), "r"(NCT) : "memory");
            asm volatile("mbarrier.init.shared.b64 [%0], %1;" :: "r"(BKE(i)), "r"(NCT) : "memory");
        }
    }
    __syncthreads();

    const int g = w >> 1;             // row group 0..7
    const int s = w & 1;              // col half
    const u32 QH = smb + OF_QH, QL = smb + OF_QL;
    float* redf = (float*)(sm + OF_RED);

    // prologue: Q hi+lo + K tile 0; single arrive covers both
    #pragma unroll
    for (int k = 0; k < 8; k++){
        int idx = tid + k * NCT;        // 0..4095
        int half = idx >> 11;
        int ci = idx & 2047;
        int row = ci >> 4, c = ci & 15;
        u32 da = (half ? QL : QH) + (u32)(row * 256) + (u32)((c ^ (row & 7)) << 4);
        const char* src = (const char*)(half ? gQL : gQH)
                        + ((size_t)(b * Mm + mrow0 + row) * 256 + c * 16);
        asm volatile("cp.async.cg.shared.global [%0], [%1], 16;" :: "r"(da), "l"(src));
    }
    cp_k(smb + OF_K0, b, 0, tid);
    mcparr(BKF(0));

    const int rA  = ((lane >> 3) & 1) * 8 + (lane & 7);
    const int cA  = ((lane >> 4) & 1) * 16;
    const int rBq = ((lane >> 4) & 1) * 8 + (lane & 7);
    const int cBq = ((lane >> 3) & 1) * 16;
    const int r0  = 16 * g + gID;

    // gmem mask word base for this thread: rows r0 and r0+8
    const u32 mkbase = ((u32)(b * Mm + mrow0 + r0)) * 64u + (u32)s;

    float o[8][4];
    #pragma unroll
    for (int i = 0; i < 8; i++){ o[i][0]=o[i][1]=o[i][2]=o[i][3]=0.f; }
    float lsum0 = 0.f, lsum1 = 0.f;
    float m0r = -1e30f, m1r = -1e30f;    // running max (exp2-arg domain), per row

    #pragma unroll 1
    for (int t = 0; t < NT; t++){
        const int kb = t % 3;
        const u32 KB = smb + OF_K0 + (u32)(kb * 32768);
        const u32 KHt = KB, KLt = KB + 16384;

        // ---- mask words for tile t: issue LDG early; used after QK+PV ----
        u32 mw0 = __ldg(&gMK[mkbase + (u32)(t * 2)]);
        u32 mw1 = __ldg(&gMK[mkbase + (u32)(t * 2) + 8u * 64u]);

        // ---- K(t) ready ----
        mwait(BKF(kb), (u32)((t / 3) & 1));

        // ---- QK: S(16x32) = Qh*Kh + Qh*Kl + Ql*Kh ----
        float s4[4][4];
        #pragma unroll
        for (int i = 0; i < 4; i++){ s4[i][0]=s4[i][1]=s4[i][2]=s4[i][3]=0.f; }

        #pragma unroll
        for (int k = 0; k < 8; k++){
            int dby = k * 32;
            u32 ah[4], al[4];
            ldsm4(ah, swa(QH, 16 * g + rA, dby + cA));
            ldsm4(al, swa(QL, 16 * g + rA, dby + cA));
            #pragma unroll
            for (int nb = 0; nb < 2; nb++){
                u32 bh[4], bl[4];
                ldsm4(bh, swa(KHt, 32 * s + nb * 16 + rBq, dby + cBq));
                ldsm4(bl, swa(KLt, 32 * s + nb * 16 + rBq, dby + cBq));
                mmaf16(s4[2*nb],   ah, bh[0], bh[1]);
                mmaf16(s4[2*nb],   ah, bl[0], bl[1]);
                mmaf16(s4[2*nb],   al, bh[0], bh[1]);
                mmaf16(s4[2*nb+1], ah, bh[2], bh[3]);
                mmaf16(s4[2*nb+1], ah, bl[2], bl[3]);
                mmaf16(s4[2*nb+1], al, bh[2], bh[3]);
            }
        }

        // ---- local per-row tile max over this warp's 32 cols ----
        {
            float t0 = fmaxf(fmaxf(s4[0][0], s4[0][1]), fmaxf(s4[1][0], s4[1][1]));
            t0 = fmaxf(t0, fmaxf(fmaxf(s4[2][0], s4[2][1]), fmaxf(s4[3][0], s4[3][1])));
            float t1 = fmaxf(fmaxf(s4[0][2], s4[0][3]), fmaxf(s4[1][2], s4[1][3]));
            t1 = fmaxf(t1, fmaxf(fmaxf(s4[2][2], s4[2][3]), fmaxf(s4[3][2], s4[3][3])));
            t0 = fmaxf(t0, __shfl_xor_sync(0xffffffffu, t0, 1));
            t0 = fmaxf(t0, __shfl_xor_sync(0xffffffffu, t0, 2));
            t1 = fmaxf(t1, __shfl_xor_sync(0xffffffffu, t1, 1));
            t1 = fmaxf(t1, __shfl_xor_sync(0xffffffffu, t1, 2));
            if (tig == 0){
                redf[r0 * 2 + s]       = t0 * C2;
                redf[(r0 + 8) * 2 + s] = t1 * C2;
            }
        }

        // ---- PV(t-1): single-pass fp16, in old scale m_{t-1} ----
        if (t > 0){
            const int kbp = (t - 1) % 3;
            const u32 KBp = smb + OF_K0 + (u32)(kbp * 32768);
            const u32 PHp = smb + OF_P0 + (u32)(((t - 1) & 1) * 16384);
            pv_step(o, PHp, KBp, g, s, rA, cA);
            marr(BKE(kbp));                    // K(t-1) consumed by this thread
        }

        // ---- pair max exchange; rescale O/lsum to new scale ----
        bar_pair(1 + g);
        float mn0, mn1;
        {
            float tm0 = fmaxf(redf[r0 * 2],       redf[r0 * 2 + 1]);
            float tm1 = fmaxf(redf[(r0 + 8) * 2], redf[(r0 + 8) * 2 + 1]);
            mn0 = fmaxf(m0r, tm0);
            mn1 = fmaxf(m1r, tm1);
            float a0 = ex2f(m0r - mn0);
            float a1 = ex2f(m1r - mn1);
            m0r = mn0; m1r = mn1;
            lsum0 *= a0; lsum1 *= a1;
            #pragma unroll
            for (int db = 0; db < 8; db++){
                o[db][0] *= a0; o[db][1] *= a0;
                o[db][2] *= a1; o[db][3] *= a1;
            }
        }

        // ---- prefetch K(t+1) ----
        if (t < NT - 1){
            if (t >= 2) mwait(BKE((t + 1) % 3), (u32)(((t + 1) / 3 - 1) & 1));
            cp_k(smb + OF_K0 + (u32)(((t + 1) % 3) * 32768), b, (t + 1) * BN, tid);
            mcparr(BKF((t + 1) % 3));
        }

        // ---- softmax (normalized) + dropout -> P[t&1] (fp16, p<=1.25) ----
        const u32 PHc = smb + OF_P0 + (u32)((t & 1) * 16384);
        #pragma unroll
        for (int nb = 0; nb < 4; nb++){
            float* c = s4[nb];
            float p0 = ex2f(fmaf(c[0], C2, -mn0));
            float p1 = ex2f(fmaf(c[1], C2, -mn0));
            float p2 = ex2f(fmaf(c[2], C2, -mn1));
            float p3 = ex2f(fmaf(c[3], C2, -mn1));
            lsum0 += p0 + p1;
            lsum1 += p2 + p3;
            int bit = 8 * nb + 2 * tig;
            float q0 = ((mw0 >> bit) & 1u)       ? p0 * INV_KEEP : 0.f;
            float q1 = ((mw0 >> (bit + 1)) & 1u) ? p1 * INV_KEEP : 0.f;
            float q2 = ((mw1 >> bit) & 1u)       ? p2 * INV_KEEP : 0.f;
            float q3 = ((mw1 >> (bit + 1)) & 1u) ? p3 * INV_KEEP : 0.f;
            int colb = 64 * s + 16 * nb + 4 * tig;
            *(u32*)(sm + (swp(PHc, r0,     colb) - smb)) = packh(q0, q1);
            *(u32*)(sm + (swp(PHc, r0 + 8, colb) - smb)) = packh(q2, q3);
        }
        bar_pair(1 + g);                       // P(t) visible within row pair
    }

    // ---- tail: PV(NT-1) ----
    {
        const int kbp = (NT - 1) % 3;
        const u32 KBp = smb + OF_K0 + (u32)(kbp * 32768);
        const u32 PHp = smb + OF_P0 + (u32)(((NT - 1) & 1) * 16384);
        pv_step(o, PHp, KBp, g, s, rA, cA);
    }

    // ---- epilogue: combine pair lsums (same scale: m synced every tile) ----
    lsum0 += __shfl_xor_sync(0xffffffffu, lsum0, 1);
    lsum0 += __shfl_xor_sync(0xffffffffu, lsum0, 2);
    lsum1 += __shfl_xor_sync(0xffffffffu, lsum1, 1);
    lsum1 += __shfl_xor_sync(0xffffffffu, lsum1, 2);
    if (tig == 0){
        redf[r0 * 2 + s]       = lsum0;
        redf[(r0 + 8) * 2 + s] = lsum1;
    }
    bar_pair(1 + g);
    {
        float inv0 = 1.0f / (redf[r0 * 2] + redf[r0 * 2 + 1]);
        float inv1 = 1.0f / (redf[(r0 + 8) * 2] + redf[(r0 + 8) * 2 + 1]);

        float* g0 = out + ((size_t)b * Mm + mrow0 + r0) * Dd + 64 * s;
        float* g1 = g0 + 8 * Dd;
        #pragma unroll
        for (int db = 0; db < 8; db++){
            int d = db * 8 + 2 * tig;
            *(float2*)(g0 + d) = make_float2(o[db][0] * inv0, o[db][1] * inv0);
            *(float2*)(g1 + d) = make_float2(o[db][2] * inv1, o[db][3] * inv1);
        }
    }
}

extern "C" void kernel_launch(void* const* d_in, const int* in_sizes, int n_in,
                              void* d_out, int out_size)
{
    const float* x1 = (const float*)d_in[0];
    const float* x2 = (const float*)d_in[1];
    float* out = (float*)d_out;

    split_mask<<<4096, 256>>>(x1, x2);

    cudaFuncSetAttribute(attn_hmma, cudaFuncAttributeMaxDynamicSharedMemorySize, SMEM_TOTAL);
    dim3 grid(Mm / BM, Bb);
    attn_hmma<<<grid, TPB, SMEM_TOTAL>>>(x1, x2, out);
}

// round 16
// speedup vs baseline: 1.0176x; 1.0176x over previous
#include <cuda_runtime.h>
#include <cuda_fp16.h>
#include <cstdint>

typedef uint32_t u32;

#define Bb 8
#define Mm 2048
#define NNs 2048
#define Dd 128
#define BM 64
#define BN 64
#define TPB 256
#define NCT 256
#define NT 32

#define C2 0.7213475204444817f   /* 0.5 * log2(e) */
#define INV_KEEP 1.25f

// pre-split fp16 copies of x1/x2 (hi/lo), packed u32 pairs, linear layout
__device__ u32 gQH[Bb*Mm*Dd/2], gQL[Bb*Mm*Dd/2];
__device__ u32 gKH[Bb*NNs*Dd/2], gKL[Bb*NNs*Dd/2];
// keep-bit words: index = (b*2048+row)*64 + col_word
__device__ u32 gMK[Bb*Mm*NNs/32];

// ---- smem byte offsets (attention kernel, per CTA = 115264 B; 2 CTAs/SM) ----
#define OF_QH   0        /* 64x128 fp16 = 16KB */
#define OF_QL   16384
#define OF_K0   32768    /* 2 x (KH 16KB + KL 16KB) ring */
#define OF_K1   65536
#define OF_P0   98304    /* 2 x PH(fp16) 8KB ring */
#define OF_P1   106496
#define OF_RED  114688   /* 64 rows x 2 floats */
#define OF_BAR  115200   /* mbarriers: KF0-1, KE0-1 (4 x 8B) */
#define SMEM_TOTAL 115264

#define BKF(i) (smb + OF_BAR + (u32)(i)*8u)
#define BKE(i) (smb + OF_BAR + 16u + (u32)(i)*8u)

__device__ __forceinline__ void mwait(u32 addr, u32 ph){
    u32 done;
    asm volatile("{\n\t.reg .pred p;\n\t"
        "mbarrier.try_wait.parity.acquire.cta.shared::cta.b64 p, [%1], %2;\n\t"
        "selp.b32 %0, 1, 0, p;\n\t}"
        : "=r"(done) : "r"(addr), "r"(ph) : "memory");
    if (!done){
        asm volatile("{\n\t.reg .pred P1;\n\t"
            "WL_%=:\n\t"
            "mbarrier.try_wait.parity.acquire.cta.shared::cta.b64 P1, [%0], %1, 0x989680;\n\t"
            "@P1 bra.uni WD_%=;\n\t"
            "bra.uni WL_%=;\n\t"
            "WD_%=:\n\t}"
            :: "r"(addr), "r"(ph) : "memory");
    }
}
__device__ __forceinline__ void marr(u32 addr){
    asm volatile("mbarrier.arrive.shared.b64 _, [%0];" :: "r"(addr) : "memory");
}
__device__ __forceinline__ void mcparr(u32 addr){
    asm volatile("cp.async.mbarrier.arrive.noinc.shared::cta.b64 [%0];" :: "r"(addr) : "memory");
}
__device__ __forceinline__ void bar_pair(int id){
    asm volatile("bar.sync %0, 64;" :: "r"(id) : "memory");
}

__device__ __forceinline__ u32 swa(u32 base, int row, int colb){
    return base + (u32)(row * 256) + (u32)((((colb >> 4) ^ (row & 7)) << 4) + (colb & 15));
}
__device__ __forceinline__ u32 swp(u32 base, int row, int colb){
    return base + (u32)(row * 128) + (u32)(((((colb >> 4) ^ (row & 7)) & 7) << 4) + (colb & 15));
}
__device__ __forceinline__ void ldsm4(u32* r, u32 a){
    asm volatile("ldmatrix.sync.aligned.m8n8.x4.shared.b16 {%0,%1,%2,%3},[%4];"
        : "=r"(r[0]),"=r"(r[1]),"=r"(r[2]),"=r"(r[3]) : "r"(a));
}
__device__ __forceinline__ void ldsm4t(u32* r, u32 a){
    asm volatile("ldmatrix.sync.aligned.m8n8.x4.trans.shared.b16 {%0,%1,%2,%3},[%4];"
        : "=r"(r[0]),"=r"(r[1]),"=r"(r[2]),"=r"(r[3]) : "r"(a));
}
__device__ __forceinline__ void mmaf16(float* c, const u32* a, u32 b0, u32 b1){
    asm volatile("mma.sync.aligned.m16n8k16.row.col.f32.f16.f16.f32 "
        "{%0,%1,%2,%3},{%4,%5,%6,%7},{%8,%9},{%0,%1,%2,%3};"
        : "+f"(c[0]),"+f"(c[1]),"+f"(c[2]),"+f"(c[3])
        : "r"(a[0]),"r"(a[1]),"r"(a[2]),"r"(a[3]),"r"(b0),"r"(b1));
}
__device__ __forceinline__ void split16(float p0, float p1, u32& h2, u32& l2){
    __half2 h = __floats2half2_rn(p0, p1);
    h2 = *(u32*)&h;
    float r0 = p0 - __low2float(h);
    float r1 = p1 - __high2float(h);
    __half2 l = __floats2half2_rn(r0, r1);
    l2 = *(u32*)&l;
}
__device__ __forceinline__ u32 packh(float a, float b){
    __half2 h = __floats2half2_rn(a, b);
    return *(u32*)&h;
}
__device__ __forceinline__ float ex2f(float x){
    float r; asm("ex2.approx.f32 %0, %1;" : "=f"(r) : "f"(x)); return r;
}

// JAX threefry2x32 partitionable, bit-exact (frozen; validated through R15).
__device__ __forceinline__ u32 tf_keep_c(u32 c)
{
    const u32 K1 = 42u;
    const u32 K2 = 0x1BD11BDAu ^ 42u;
    u32 x0 = c;
    u32 x1 = __funnelshift_l(c, c, 13) ^ c;
#define TF_RND(r) { x0 += x1; x1 = __funnelshift_l(x1, x1, (r)); x1 ^= x0; }
    TF_RND(15) TF_RND(26) TF_RND(6)
    x0 += K1; x1 += K2 + 1u;
    TF_RND(17) TF_RND(29) TF_RND(16) TF_RND(24)
    x0 += K2; x1 += 0u + 2u;
    TF_RND(13) TF_RND(15) TF_RND(26) TF_RND(6)
    x0 += 0u; x1 += K1 + 3u;
    TF_RND(17) TF_RND(29) TF_RND(16) TF_RND(24)
    x0 += K1; x1 += K2 + 4u;
    TF_RND(13) TF_RND(15) TF_RND(26) TF_RND(6)
    x0 += K2; x1 += 0u + 5u;
#undef TF_RND
    return (((x0 ^ x1) >> 9) <= 6710886u) ? 1u : 0u;
}

// ---------------------------------------------------------------------------
// Kernel A: split x1/x2 -> fp16 hi/lo AND generate all keep-bit words.
// ---------------------------------------------------------------------------
__global__ void __launch_bounds__(256)
split_mask(const float* __restrict__ x1, const float* __restrict__ x2)
{
    int i = blockIdx.x * 256 + threadIdx.x;
    {
        int half = i >> 19;
        int j = i & 0x7FFFF;
        const float4* src = (const float4*)(half ? x2 : x1);
        float4 v = src[j];
        u32 h0,l0,h1,l1;
        split16(v.x, v.y, h0, l0);
        split16(v.z, v.w, h1, l1);
        uint2* dh = (uint2*)(half ? gKH : gQH);
        uint2* dl = (uint2*)(half ? gKL : gQL);
        dh[j] = make_uint2(h0, h1);
        dl[j] = make_uint2(l0, l1);
    }
    {
        u32 rowg = (u32)i >> 6;
        u32 colw = (u32)i & 63u;
        u32 cbase = rowg * 2048u + colw * 32u + 42u;
        u32 m = 0;
        #pragma unroll 8
        for (int j = 0; j < 32; j++)
            m |= tf_keep_c(cbase + (u32)j) << j;
        gMK[i] = m;
    }
}

// cp.async one 64-row fp16 K tile pair (hi+lo); 256 threads, 8 chunks each
__device__ __forceinline__ void cp_k(u32 bufbase, int b, int n0, int tid){
    #pragma unroll
    for (int k = 0; k < 8; k++){
        int idx  = tid + k * NCT;           // 0..2047
        int half = idx >> 10;
        int ci   = idx & 1023;
        int row  = ci >> 4;
        int c    = ci & 15;
        u32 da = bufbase + (u32)(half * 16384) + (u32)(row * 256) + (u32)((c ^ (row & 7)) << 4);
        const char* s = (const char*)(half ? gKL : gKH)
                      + ((size_t)(b * NNs + n0 + row) * 256 + c * 16);
        asm volatile("cp.async.cg.shared.global [%0], [%1], 16;" :: "r"(da), "l"(s));
    }
}

// PV step (single pass fp16): O += P16 * V16  (V16 = fp16 K-hi tile, trans)
__device__ __forceinline__ void pv_step(float o[8][4], u32 PHb, u32 KHb,
                                        int g, int s, int rA, int cA){
    #pragma unroll
    for (int kk = 0; kk < 4; kk++){
        u32 pA[4];
        ldsm4(pA, swp(PHb, 16 * g + rA, 32 * kk + cA));
        #pragma unroll
        for (int dgp = 0; dgp < 4; dgp++){
            int colb = 128 * s + 32 * dgp + cA;
            u32 bh[4];
            ldsm4t(bh, swa(KHb, 16 * kk + rA, colb));
            mmaf16(o[2*dgp],   pA, bh[0], bh[1]);
            mmaf16(o[2*dgp+1], pA, bh[2], bh[3]);
        }
    }
}

// ---------------------------------------------------------------------------
// Kernel B: attention. BM=64, 256 threads, 2 CTAs/SM. Masks via __ldg.
// ---------------------------------------------------------------------------
__global__ void __launch_bounds__(TPB, 2)
attn_hmma(const float* __restrict__ x1, const float* __restrict__ x2, float* __restrict__ out)
{
    extern __shared__ char sm[];
    const u32 smb = (u32)__cvta_generic_to_shared(sm);
    const int tid  = threadIdx.x;
    const int w    = tid >> 5;
    const int lane = tid & 31;
    const int gID  = lane >> 2;
    const int tig  = lane & 3;
    const int b    = blockIdx.y;
    const int mrow0 = blockIdx.x * BM;

    if (tid == 0){
        #pragma unroll
        for (int i = 0; i < 2; i++){
            asm volatile("mbarrier.init.shared.b64 [%0], %1;" :: "r"(BKF(i)), "r"(NCT) : "memory");
            asm volatile("mbarrier.init.shared.b64 [%0], %1;" :: "r"(BKE(i)), "r"(NCT) : "memory");
        }
    }
    __syncthreads();

    const int g = w >> 1;             // row group 0..3: rows 16g..16g+15
    const int s = w & 1;              // col half
    const u32 QH = smb + OF_QH, QL = smb + OF_QL;
    float* redf = (float*)(sm + OF_RED);

    // prologue: Q hi+lo (2048 chunks) + K tile 0; single arrive covers both
    #pragma unroll
    for (int k = 0; k < 8; k++){
        int idx = tid + k * NCT;        // 0..2047
        int half = idx >> 10;
        int ci = idx & 1023;
        int row = ci >> 4, c = ci & 15;
        u32 da = (half ? QL : QH) + (u32)(row * 256) + (u32)((c ^ (row & 7)) << 4);
        const char* src = (const char*)(half ? gQL : gQH)
                        + ((size_t)(b * Mm + mrow0 + row) * 256 + c * 16);
        asm volatile("cp.async.cg.shared.global [%0], [%1], 16;" :: "r"(da), "l"(src));
    }
    cp_k(smb + OF_K0, b, 0, tid);
    mcparr(BKF(0));
    // prefetch K(1) immediately (buffer 1 fresh)
    cp_k(smb + OF_K1, b, BN, tid);
    mcparr(BKF(1));

    const int rA  = ((lane >> 3) & 1) * 8 + (lane & 7);
    const int cA  = ((lane >> 4) & 1) * 16;
    const int rBq = ((lane >> 4) & 1) * 8 + (lane & 7);
    const int cBq = ((lane >> 3) & 1) * 16;
    const int r0  = 16 * g + gID;

    const u32 mkbase = ((u32)(b * Mm + mrow0 + r0)) * 64u + (u32)s;

    float o[8][4];
    #pragma unroll
    for (int i = 0; i < 8; i++){ o[i][0]=o[i][1]=o[i][2]=o[i][3]=0.f; }
    float lsum0 = 0.f, lsum1 = 0.f;
    float m0r = -1e30f, m1r = -1e30f;

    #pragma unroll 1
    for (int t = 0; t < NT; t++){
        const int kb = t & 1;
        const u32 KB = smb + OF_K0 + (u32)(kb * 32768);
        const u32 KHt = KB, KLt = KB + 16384;

        // ---- mask words for tile t (early LDG; consumed after QK+PV) ----
        u32 mw0 = __ldg(&gMK[mkbase + (u32)(t * 2)]);
        u32 mw1 = __ldg(&gMK[mkbase + (u32)(t * 2) + 8u * 64u]);

        // ---- K(t) ready: use #(t/2) of buffer kb ----
        mwait(BKF(kb), (u32)((t >> 1) & 1));

        // ---- QK: S(16x32) = Qh*Kh + Qh*Kl + Ql*Kh ----
        float s4[4][4];
        #pragma unroll
        for (int i = 0; i < 4; i++){ s4[i][0]=s4[i][1]=s4[i][2]=s4[i][3]=0.f; }

        #pragma unroll
        for (int k = 0; k < 8; k++){
            int dby = k * 32;
            u32 ah[4], al[4];
            ldsm4(ah, swa(QH, 16 * g + rA, dby + cA));
            ldsm4(al, swa(QL, 16 * g + rA, dby + cA));
            #pragma unroll
            for (int nb = 0; nb < 2; nb++){
                u32 bh[4], bl[4];
                ldsm4(bh, swa(KHt, 32 * s + nb * 16 + rBq, dby + cBq));
                ldsm4(bl, swa(KLt, 32 * s + nb * 16 + rBq, dby + cBq));
                mmaf16(s4[2*nb],   ah, bh[0], bh[1]);
                mmaf16(s4[2*nb],   ah, bl[0], bl[1]);
                mmaf16(s4[2*nb],   al, bh[0], bh[1]);
                mmaf16(s4[2*nb+1], ah, bh[2], bh[3]);
                mmaf16(s4[2*nb+1], ah, bl[2], bl[3]);
                mmaf16(s4[2*nb+1], al, bh[2], bh[3]);
            }
        }

        // ---- local per-row tile max ----
        {
            float t0 = fmaxf(fmaxf(s4[0][0], s4[0][1]), fmaxf(s4[1][0], s4[1][1]));
            t0 = fmaxf(t0, fmaxf(fmaxf(s4[2][0], s4[2][1]), fmaxf(s4[3][0], s4[3][1])));
            float t1 = fmaxf(fmaxf(s4[0][2], s4[0][3]), fmaxf(s4[1][2], s4[1][3]));
            t1 = fmaxf(t1, fmaxf(fmaxf(s4[2][2], s4[2][3]), fmaxf(s4[3][2], s4[3][3])));
            t0 = fmaxf(t0, __shfl_xor_sync(0xffffffffu, t0, 1));
            t0 = fmaxf(t0, __shfl_xor_sync(0xffffffffu, t0, 2));
            t1 = fmaxf(t1, __shfl_xor_sync(0xffffffffu, t1, 1));
            t1 = fmaxf(t1, __shfl_xor_sync(0xffffffffu, t1, 2));
            if (tig == 0){
                redf[r0 * 2 + s]       = t0 * C2;
                redf[(r0 + 8) * 2 + s] = t1 * C2;
            }
        }

        // ---- PV(t-1): uses K buffer (t-1)&1 and P buffer (t-1)&1 ----
        if (t > 0){
            const u32 KBp = smb + OF_K0 + (u32)(((t - 1) & 1) * 32768);
            const u32 PHp = smb + OF_P0 + (u32)(((t - 1) & 1) * 8192);
            pv_step(o, PHp, KBp, g, s, rA, cA);
            marr(BKE((t - 1) & 1));            // K(t-1) consumed by this thread
        }

        // ---- prefetch K(t+1) into buffer (t+1)&1 == (t-1)&1 (freed above) ----
        if (t >= 1 && t < NT - 1){
            mwait(BKE((t + 1) & 1), (u32)((((t + 1) >> 1) - 1) & 1));
            cp_k(smb + OF_K0 + (u32)(((t + 1) & 1) * 32768), b, (t + 1) * BN, tid);
            mcparr(BKF((t + 1) & 1));
        }

        // ---- pair max exchange; rescale O/lsum ----
        bar_pair(1 + g);
        float mn0, mn1;
        {
            float tm0 = fmaxf(redf[r0 * 2],       redf[r0 * 2 + 1]);
            float tm1 = fmaxf(redf[(r0 + 8) * 2], redf[(r0 + 8) * 2 + 1]);
            mn0 = fmaxf(m0r, tm0);
            mn1 = fmaxf(m1r, tm1);
            float a0 = ex2f(m0r - mn0);
            float a1 = ex2f(m1r - mn1);
            m0r = mn0; m1r = mn1;
            lsum0 *= a0; lsum1 *= a1;
            #pragma unroll
            for (int db = 0; db < 8; db++){
                o[db][0] *= a0; o[db][1] *= a0;
                o[db][2] *= a1; o[db][3] *= a1;
            }
        }

        // ---- softmax (normalized) + dropout -> P[t&1] (fp16) ----
        const u32 PHc = smb + OF_P0 + (u32)((t & 1) * 8192);
        #pragma unroll
        for (int nb = 0; nb < 4; nb++){
            float* c = s4[nb];
            float p0 = ex2f(fmaf(c[0], C2, -mn0));
            float p1 = ex2f(fmaf(c[1], C2, -mn0));
            float p2 = ex2f(fmaf(c[2], C2, -mn1));
            float p3 = ex2f(fmaf(c[3], C2, -mn1));
            lsum0 += p0 + p1;
            lsum1 += p2 + p3;
            int bit = 8 * nb + 2 * tig;
            float q0 = ((mw0 >> bit) & 1u)       ? p0 * INV_KEEP : 0.f;
            float q1 = ((mw0 >> (bit + 1)) & 1u) ? p1 * INV_KEEP : 0.f;
            float q2 = ((mw1 >> bit) & 1u)       ? p2 * INV_KEEP : 0.f;
            float q3 = ((mw1 >> (bit + 1)) & 1u) ? p3 * INV_KEEP : 0.f;
            int colb = 64 * s + 16 * nb + 4 * tig;
            *(u32*)(sm + (swp(PHc, r0,     colb) - smb)) = packh(q0, q1);
            *(u32*)(sm + (swp(PHc, r0 + 8, colb) - smb)) = packh(q2, q3);
        }
        bar_pair(1 + g);                       // P(t) visible within row pair
    }

    // ---- tail: PV(NT-1) ----
    {
        const u32 KBp = smb + OF_K0 + (u32)(((NT - 1) & 1) * 32768);
        const u32 PHp = smb + OF_P0 + (u32)(((NT - 1) & 1) * 8192);
        pv_step(o, PHp, KBp, g, s, rA, cA);
    }

    // ---- epilogue ----
    lsum0 += __shfl_xor_sync(0xffffffffu, lsum0, 1);
    lsum0 += __shfl_xor_sync(0xffffffffu, lsum0, 2);
    lsum1 += __shfl_xor_sync(0xffffffffu, lsum1, 1);
    lsum1 += __shfl_xor_sync(0xffffffffu, lsum1, 2);
    if (tig == 0){
        redf[r0 * 2 + s]       = lsum0;
        redf[(r0 + 8) * 2 + s] = lsum1;
    }
    bar_pair(1 + g);
    {
        float inv0 = 1.0f / (redf[r0 * 2] + redf[r0 * 2 + 1]);
        float inv1 = 1.0f / (redf[(r0 + 8) * 2] + redf[(r0 + 8) * 2 + 1]);

        float* g0 = out + ((size_t)b * Mm + mrow0 + r0) * Dd + 64 * s;
        float* g1 = g0 + 8 * Dd;
        #pragma unroll
        for (int db = 0; db < 8; db++){
            int d = db * 8 + 2 * tig;
            *(float2*)(g0 + d) = make_float2(o[db][0] * inv0, o[db][1] * inv0);
            *(float2*)(g1 + d) = make_float2(o[db][2] * inv1, o[db][3] * inv1);
        }
    }
}

extern "C" void kernel_launch(void* const* d_in, const int* in_sizes, int n_in,
                              void* d_out, int out_size)
{
    const float* x1 = (const float*)d_in[0];
    const float* x2 = (const float*)d_in[1];
    float* out = (float*)d_out;

    split_mask<<<4096, 256>>>(x1, x2);

    cudaFuncSetAttribute(attn_hmma, cudaFuncAttributeMaxDynamicSharedMemorySize, SMEM_TOTAL);
    dim3 grid(Mm / BM, Bb);
    attn_hmma<<<grid, TPB, SMEM_TOTAL>>>(x1, x2, out);
}